// round 10
// baseline (speedup 1.0000x reference)
#include <cuda_runtime.h>

// GaussianKernelBiasingDensity: out_b = -f(z_b)^T (W+eps) g(t_b)
// Separable: f_i(z)=exp(-50(z-zm_i)^2), g_j(t)=exp(-50(t-tm_j)^2).
// R8: 4-way i-split (grid 256->1024 blocks) to fix grid-limited occupancy;
//     deterministic cross-block combine via static scratch + reduce kernel.

#define T_BINS 128
#define Z_BINS 128
#define NTHREADS 256
#define BPB 64          // batch elements per block (2 per thread-lane)
#define JS 16           // j-slice per warp (8 warps * 16 = 128)
#define SPLIT 4         // i-range split factor
#define ICHUNK (Z_BINS / SPLIT)   // 32 i-rows per block
#define NMAX 16384

typedef unsigned long long u64;

__device__ float g_scratch[SPLIT][NMAX];   // per-chunk partial sums

__device__ __forceinline__ float ex2f(float x) {
    float r; asm("ex2.approx.ftz.f32 %0, %1;" : "=f"(r) : "f"(x)); return r;
}
__device__ __forceinline__ u64 fma2(u64 a, u64 b, u64 c) {
    u64 d; asm("fma.rn.f32x2 %0, %1, %2, %3;" : "=l"(d) : "l"(a), "l"(b), "l"(c));
    return d;
}
__device__ __forceinline__ u64 dup2(float x) {
    u64 d; asm("mov.b64 %0, {%1, %1};" : "=l"(d) : "f"(x)); return d;
}
__device__ __forceinline__ u64 pack2(float lo, float hi) {
    u64 d; asm("mov.b64 %0, {%1, %2};" : "=l"(d) : "f"(lo), "f"(hi)); return d;
}
__device__ __forceinline__ float2 unpack2(u64 v) {
    float2 r; asm("mov.b64 {%0, %1}, %2;" : "=f"(r.x), "=f"(r.y) : "l"(v)); return r;
}

__global__ __launch_bounds__(NTHREADS, 3)
void gkb_kernel(const float* __restrict__ Zv,
                const float* __restrict__ Tv,
                const float* __restrict__ means,
                const float* __restrict__ weights,
                int n)
{
    __shared__ float  Wsh[ICHUNK * T_BINS];   // 4096 floats (W slice + eps)
    __shared__ float2 ABz[ICHUNK];            // 32 x {A, B} for this chunk
    __shared__ float2 ABt[T_BINS];            // 128 x {A, B}
    __shared__ float2 red[NTHREADS];          // cross-warp reduction

    const float L2E = 1.4426950408889634f;
    const float EPS = 0.01f;
    int tid = threadIdx.x;

    int chunk = blockIdx.x & (SPLIT - 1);
    int group = blockIdx.x >> 2;              // log2(SPLIT) = 2
    int i0    = chunk * ICHUNK;

    // ---- stage W' slice (rows i0..i0+ICHUNK) = weights + eps ----
    const float4* w4  = (const float4*)(weights + i0 * T_BINS);
    float4*       ws4 = (float4*)Wsh;
    #pragma unroll
    for (int k = tid; k < (ICHUNK * T_BINS) / 4; k += NTHREADS) {
        float4 v = w4[k];
        v.x += EPS; v.y += EPS; v.z += EPS; v.w += EPS;
        ws4[k] = v;
    }
    // ---- per-bin exp constants (log2e folded): arg = z*A + (B + base) ----
    if (tid < ICHUNK) {
        float zm = means[(i0 + tid) * (T_BINS * 2)];   // means[i][0][0]
        ABz[tid] = make_float2(100.f * L2E * zm, -50.f * L2E * zm * zm);
    }
    if (tid < T_BINS) {
        float tm = means[tid * 2 + 1];                 // means[0][j][1]
        ABt[tid] = make_float2(100.f * L2E * tm, -50.f * L2E * tm * tm);
    }
    __syncthreads();

    int lane = tid & 31;
    int w    = tid >> 5;
    int ba   = group * BPB + lane;          // batch element A
    int bb   = ba + 32;                     // batch element B
    bool va = (ba < n), vb = (bb < n);

    float za = va ? Zv[ba] : 0.f,  ta = va ? Tv[ba] : 0.f;
    float zb = vb ? Zv[bb] : 0.f,  tb = vb ? Tv[bb] : 0.f;
    float baseza = -50.f * L2E * za * za;
    float basezb = -50.f * L2E * zb * zb;
    float baseta = -50.f * L2E * ta * ta;
    float basetb = -50.f * L2E * tb * tb;

    // ---- main loop over this block's i-chunk ----
    u64 ha[JS/2], hb[JS/2];
    #pragma unroll
    for (int q = 0; q < JS/2; q++) { ha[q] = 0ull; hb[q] = 0ull; }

    const int joff = w * JS;
    #pragma unroll 4
    for (int i = 0; i < ICHUNK; i++) {
        float2 ab = ABz[i];                               // LDS.64 broadcast
        float fa = ex2f(fmaf(za, ab.x, ab.y + baseza));
        float fb = ex2f(fmaf(zb, ab.x, ab.y + basezb));
        u64 fa2 = dup2(fa), fb2 = dup2(fb);
        const ulonglong2* wr = (const ulonglong2*)(Wsh + i * T_BINS + joff);
        #pragma unroll
        for (int q = 0; q < 4; q++) {
            ulonglong2 wv = wr[q];                        // LDS.128 broadcast
            ha[2*q+0] = fma2(fa2, wv.x, ha[2*q+0]);
            ha[2*q+1] = fma2(fa2, wv.y, ha[2*q+1]);
            hb[2*q+0] = fma2(fb2, wv.x, hb[2*q+0]);
            hb[2*q+1] = fma2(fb2, wv.y, hb[2*q+1]);
        }
    }

    // ---- epilogue: packed dot with g ----
    u64 acca = 0ull, accb = 0ull;
    #pragma unroll
    for (int q = 0; q < JS/2; q++) {
        float2 ab0 = ABt[joff + 2*q + 0];
        float2 ab1 = ABt[joff + 2*q + 1];
        float ga0 = ex2f(fmaf(ta, ab0.x, ab0.y + baseta));
        float ga1 = ex2f(fmaf(ta, ab1.x, ab1.y + baseta));
        float gb0 = ex2f(fmaf(tb, ab0.x, ab0.y + basetb));
        float gb1 = ex2f(fmaf(tb, ab1.x, ab1.y + basetb));
        acca = fma2(pack2(ga0, ga1), ha[q], acca);
        accb = fma2(pack2(gb0, gb1), hb[q], accb);
    }
    float2 pa = unpack2(acca), pb = unpack2(accb);
    red[w * 32 + lane] = make_float2(pa.x + pa.y, pb.x + pb.y);
    __syncthreads();

    // ---- reduce 8 warp-partials, write chunk partial to scratch ----
    if (w == 0) {
        float sa = 0.f, sb = 0.f;
        #pragma unroll
        for (int k = 0; k < 8; k++) {
            float2 v = red[k * 32 + lane];
            sa += v.x; sb += v.y;
        }
        if (va) g_scratch[chunk][ba] = sa;
        if (vb) g_scratch[chunk][bb] = sb;
    }
}

__global__ __launch_bounds__(256)
void gkb_reduce(float* __restrict__ out, int n) {
    int b = blockIdx.x * blockDim.x + threadIdx.x;
    if (b < n) {
        float s = g_scratch[0][b] + g_scratch[1][b]
                + g_scratch[2][b] + g_scratch[3][b];
        out[b] = -s;
    }
}

extern "C" void kernel_launch(void* const* d_in, const int* in_sizes, int n_in,
                              void* d_out, int out_size) {
    const float* z       = (const float*)d_in[0];
    const float* t       = (const float*)d_in[1];
    const float* means   = (const float*)d_in[2];
    const float* weights = (const float*)d_in[3];
    float* out = (float*)d_out;
    int n = in_sizes[0];

    int groups = (n + BPB - 1) / BPB;          // 256 for B=16384
    gkb_kernel<<<groups * SPLIT, NTHREADS>>>(z, t, means, weights, n);
    gkb_reduce<<<(n + 255) / 256, 256>>>(out, n);
}